// round 7
// baseline (speedup 1.0000x reference)
#include <cuda_runtime.h>
#include <cuda_bf16.h>
#include <cstdint>
#include <math.h>

// Problem dims
#define BB 4
#define SS 1024
#define DM 1024
#define NH 16
#define DK 64
#define DV 64

// Scratch for projected Q/K/V in [b, h, s, d] layout (stored tf32-rounded)
__device__ float g_Q[BB * NH * SS * DK];
__device__ float g_K[BB * NH * SS * DK];
__device__ float g_V[BB * NH * SS * DV];

// ---------------------------------------------------------------------------
// helpers
// ---------------------------------------------------------------------------
__device__ __forceinline__ uint32_t f2tf32(float x) {
    uint32_t r;
    asm("cvt.rna.tf32.f32 %0, %1;" : "=r"(r) : "f"(x));
    return r;
}
__device__ __forceinline__ float rnd_tf32(float x) {
    return __uint_as_float(f2tf32(x));
}

__device__ __forceinline__ void mma_tf32(float c[4], const uint32_t a[4], const uint32_t b[2]) {
    asm volatile(
        "mma.sync.aligned.m16n8k8.row.col.f32.tf32.tf32.f32 "
        "{%0,%1,%2,%3}, {%4,%5,%6,%7}, {%8,%9}, {%0,%1,%2,%3};"
        : "+f"(c[0]), "+f"(c[1]), "+f"(c[2]), "+f"(c[3])
        : "r"(a[0]), "r"(a[1]), "r"(a[2]), "r"(a[3]), "r"(b[0]), "r"(b[1]));
}

__device__ __forceinline__ void ldsm_x4(uint32_t r[4], uint32_t addr) {
    asm volatile("ldmatrix.sync.aligned.m8n8.x4.shared.b16 {%0,%1,%2,%3}, [%4];"
                 : "=r"(r[0]), "=r"(r[1]), "=r"(r[2]), "=r"(r[3]) : "r"(addr));
}

__device__ __forceinline__ void cp16(uint32_t smem, const void* g) {
    asm volatile("cp.async.cg.shared.global [%0], [%1], 16;" :: "r"(smem), "l"(g));
}
#define CP_COMMIT() asm volatile("cp.async.commit_group;")
#define CP_WAIT0()  asm volatile("cp.async.wait_group 0;")

// ---------------------------------------------------------------------------
// Projection GEMM, tf32 mma.sync (unchanged from R5: proven 193us).
// ---------------------------------------------------------------------------
#define ASTR 36
#define WSTR 136

__global__ __launch_bounds__(256, 2) void proj_mma_kernel(
    const float* __restrict__ xq, const float* __restrict__ xk, const float* __restrict__ xv,
    const float* __restrict__ wq, const float* __restrict__ wk, const float* __restrict__ wv,
    const float* __restrict__ bq, const float* __restrict__ bk, const float* __restrict__ bv)
{
    __shared__ float As[128 * ASTR];
    __shared__ float Ws[32 * WSTR];

    const float* X; const float* W; const float* bias; float* out;
    int which = blockIdx.z;
    if (which == 0)      { X = xq; W = wq; bias = bq; out = g_Q; }
    else if (which == 1) { X = xk; W = wk; bias = bk; out = g_K; }
    else                 { X = xv; W = wv; bias = bv; out = g_V; }

    const int tid  = threadIdx.x;
    const int warp = tid >> 5;
    const int lane = tid & 31;
    const int wm   = warp >> 2;
    const int wn   = warp & 3;
    const int tileM = blockIdx.y * 128;
    const int tileN = blockIdx.x * 128;

    const int lrow = (lane & 7) + ((lane >> 3) & 1) * 8;
    const int lkc  = (lane >> 4) * 4;
    const int a_lane_off = lrow * ASTR + lkc;

    const uint32_t As_base = (uint32_t)__cvta_generic_to_shared(As);

    float acc[4][4][4];
#pragma unroll
    for (int mt = 0; mt < 4; mt++)
#pragma unroll
        for (int nt = 0; nt < 4; nt++)
#pragma unroll
            for (int i = 0; i < 4; i++) acc[mt][nt][i] = 0.0f;

    float4 xr[4], wr[4];
#pragma unroll
    for (int p = 0; p < 4; p++) {
        int id = tid + 256 * p;
        xr[p] = *(const float4*)&X[(size_t)(tileM + (id >> 3)) * DM + (id & 7) * 4];
        wr[p] = *(const float4*)&W[(size_t)(id >> 5) * DM + tileN + (id & 31) * 4];
    }

    for (int k0 = 0; k0 < DM; k0 += 32) {
        __syncthreads();
#pragma unroll
        for (int p = 0; p < 4; p++) {
            int id = tid + 256 * p;
            float4 xv4 = make_float4(rnd_tf32(xr[p].x), rnd_tf32(xr[p].y),
                                     rnd_tf32(xr[p].z), rnd_tf32(xr[p].w));
            float4 wv4 = make_float4(rnd_tf32(wr[p].x), rnd_tf32(wr[p].y),
                                     rnd_tf32(wr[p].z), rnd_tf32(wr[p].w));
            *(float4*)&As[(id >> 3) * ASTR + (id & 7) * 4] = xv4;
            *(float4*)&Ws[(id >> 5) * WSTR + (id & 31) * 4] = wv4;
        }
        __syncthreads();

        if (k0 + 32 < DM) {
#pragma unroll
            for (int p = 0; p < 4; p++) {
                int id = tid + 256 * p;
                xr[p] = *(const float4*)&X[(size_t)(tileM + (id >> 3)) * DM + k0 + 32 + (id & 7) * 4];
                wr[p] = *(const float4*)&W[(size_t)(k0 + 32 + (id >> 5)) * DM + tileN + (id & 31) * 4];
            }
        }

#pragma unroll
        for (int ks = 0; ks < 4; ks++) {
            uint32_t a[4][4];
#pragma unroll
            for (int mt = 0; mt < 4; mt++) {
                uint32_t addr = As_base +
                    4u * (uint32_t)((wm * 64 + mt * 16) * ASTR + ks * 8 + a_lane_off);
                ldsm_x4(a[mt], addr);
            }
            uint32_t bfr[4][2];
#pragma unroll
            for (int nt = 0; nt < 4; nt++) {
                int col = wn * 32 + nt * 8 + (lane >> 2);
                int krow = ks * 8 + (lane & 3);
                bfr[nt][0] = __float_as_uint(Ws[krow * WSTR + col]);
                bfr[nt][1] = __float_as_uint(Ws[(krow + 4) * WSTR + col]);
            }
#pragma unroll
            for (int mt = 0; mt < 4; mt++)
#pragma unroll
                for (int nt = 0; nt < 4; nt++)
                    mma_tf32(acc[mt][nt], a[mt], bfr[nt]);
        }
    }

#pragma unroll
    for (int mt = 0; mt < 4; mt++) {
        int r0 = tileM + wm * 64 + mt * 16 + (lane >> 2);
#pragma unroll
        for (int nt = 0; nt < 4; nt++) {
            int c0 = tileN + wn * 32 + nt * 8 + (lane & 3) * 2;
            int h = c0 >> 6, d = c0 & 63;
            float bv0 = bias[c0], bv1 = bias[c0 + 1];
#pragma unroll
            for (int half = 0; half < 2; half++) {
                int r = r0 + half * 8;
                int bb = r >> 10, s = r & (SS - 1);
                float2 o = make_float2(rnd_tf32(acc[mt][nt][half * 2 + 0] + bv0),
                                       rnd_tf32(acc[mt][nt][half * 2 + 1] + bv1));
                *(float2*)&out[(((size_t)(bb * NH + h) * SS + s) << 6) + d] = o;
            }
        }
    }
}

// ---------------------------------------------------------------------------
// Fused attention: R5 tiling (32 q-rows, 128-row K/V tiles, ~210KB smem,
// 1 CTA/SM) but 512 threads / 16 warps to cover phase latency.
// Scores: warp w -> (mt = w>>3, cols (w&7)*16..+16). Softmax: 2 rows/warp.
// PV: warp w -> (mt = w>>3, d-cols (w&7)*8..+8).
// ---------------------------------------------------------------------------
#define QR 32
#define KT 128
#define SQS 68
#define SKS 68
#define SSS 1028
#define ATTN_SMEM_FLOATS (QR * SQS + 2 * KT * SKS + QR * SSS)
#define ATTN_SMEM_BYTES (ATTN_SMEM_FLOATS * 4)

__global__ __launch_bounds__(512, 1) void attn_kernel(
    float* __restrict__ ctx_out, float* __restrict__ attn_out)
{
    extern __shared__ float sm[];
    float* sQ  = sm;                        // 32 x 68
    float* sB0 = sQ + QR * SQS;             // 128 x 68 (buf 0)
    float* sB1 = sB0 + KT * SKS;            // 128 x 68 (buf 1)
    float* sS  = sB1 + KT * SKS;            // 32 x 1028

    const int tid  = threadIdx.x;
    const int warp = tid >> 5;      // 0..15
    const int lane = tid & 31;
    const int wmt  = warp >> 3;     // 0..1 : m16 tile
    const int wns  = warp & 7;      // 0..7 : n-slice
    const int qt = blockIdx.x;
    const int h  = blockIdx.y;
    const int b  = blockIdx.z;

    const float* Qb = g_Q + ((size_t)(b * NH + h) * SS + qt * QR) * DK;
    const float* Kb = g_K + (size_t)(b * NH + h) * SS * DK;
    const float* Vb = g_V + (size_t)(b * NH + h) * SS * DV;

    const int lrow = (lane & 7) + ((lane >> 3) & 1) * 8;
    const int lkc  = (lane >> 4) * 4;
    const uint32_t sQ_base = (uint32_t)__cvta_generic_to_shared(sQ);
    const uint32_t sS_base = (uint32_t)__cvta_generic_to_shared(sS);
    const uint32_t buf_base[2] = {
        (uint32_t)__cvta_generic_to_shared(sB0),
        (uint32_t)__cvta_generic_to_shared(sB1)
    };
    float* const buf_ptr[2] = { sB0, sB1 };

    // tile-copy coords: 128x64 tile = 2048 float4, 512 threads -> 4 each
    const int crow = tid >> 4;          // 0..31 (+32 per p)
    const int cc4  = (tid & 15) * 4;

    // ---- issue Q + K0 ----
    {
        int row = tid >> 4;   // 0..31, one float4 per thread
        cp16(sQ_base + 4u * (uint32_t)(row * SQS + cc4), &Qb[row * DK + cc4]);
    }
#pragma unroll
    for (int p = 0; p < 4; p++) {
        int row = crow + 32 * p;
        cp16(buf_base[0] + 4u * (uint32_t)(row * SKS + cc4), &Kb[row * DK + cc4]);
    }
    CP_COMMIT();
    CP_WAIT0();
    __syncthreads();

    // Preload Q fragments for this warp's m16 tile (raw bits, pre-rounded)
    uint32_t aq[8][4];
#pragma unroll
    for (int ks = 0; ks < 8; ks++)
        ldsm_x4(aq[ks], sQ_base + 4u * (uint32_t)((wmt * 16 + lrow) * SQS + ks * 8 + lkc));

    // ---- Scores: S = (Q K^T)/8 ----
    for (int kt = 0; kt < SS / KT; kt++) {
        {
            const float* src = (kt < SS / KT - 1) ? &Kb[(kt + 1) * KT * DK] : &Vb[0];
            uint32_t nb = buf_base[(kt + 1) & 1];
#pragma unroll
            for (int p = 0; p < 4; p++) {
                int row = crow + 32 * p;
                cp16(nb + 4u * (uint32_t)(row * SKS + cc4), &src[row * DK + cc4]);
            }
            CP_COMMIT();
        }

        const float* kb = buf_ptr[kt & 1];
        float c[2][4];
#pragma unroll
        for (int nt = 0; nt < 2; nt++)
#pragma unroll
            for (int i = 0; i < 4; i++) c[nt][i] = 0.0f;

#pragma unroll
        for (int ks = 0; ks < 8; ks++) {
            uint32_t bfr[2][2];
#pragma unroll
            for (int nt = 0; nt < 2; nt++) {
                int ncol = wns * 16 + nt * 8 + (lane >> 2);
                int krow = ks * 8 + (lane & 3);
                bfr[nt][0] = __float_as_uint(kb[ncol * SKS + krow]);
                bfr[nt][1] = __float_as_uint(kb[ncol * SKS + krow + 4]);
            }
            mma_tf32(c[0], aq[ks], bfr[0]);
            mma_tf32(c[1], aq[ks], bfr[1]);
        }
#pragma unroll
        for (int nt = 0; nt < 2; nt++) {
            int r = wmt * 16 + (lane >> 2);
            int col = kt * KT + wns * 16 + nt * 8 + 2 * (lane & 3);
            *(float2*)&sS[r * SSS + col] = make_float2(c[nt][0] * 0.125f, c[nt][1] * 0.125f);
            *(float2*)&sS[(r + 8) * SSS + col] = make_float2(c[nt][2] * 0.125f, c[nt][3] * 0.125f);
        }

        CP_WAIT0();
        __syncthreads();
    }

    // ---- Softmax (2 rows/warp); raw P -> gmem, tf32 P -> smem ----
#pragma unroll
    for (int rr = 0; rr < 2; rr++) {
        int r = warp * 2 + rr;
        float* row = sS + r * SSS;
        float mx = -3.0e38f;
#pragma unroll
        for (int k = 0; k < 8; k++) {
            float4 v = *(const float4*)&row[lane * 4 + 128 * k];
            mx = fmaxf(mx, fmaxf(fmaxf(v.x, v.y), fmaxf(v.z, v.w)));
        }
#pragma unroll
        for (int o = 16; o > 0; o >>= 1) mx = fmaxf(mx, __shfl_xor_sync(0xffffffffu, mx, o));
        float sum = 0.0f;
        float4 e[8];
#pragma unroll
        for (int k = 0; k < 8; k++) {
            float4 v = *(const float4*)&row[lane * 4 + 128 * k];
            e[k].x = __expf(v.x - mx); e[k].y = __expf(v.y - mx);
            e[k].z = __expf(v.z - mx); e[k].w = __expf(v.w - mx);
            sum += e[k].x + e[k].y + e[k].z + e[k].w;
        }
#pragma unroll
        for (int o = 16; o > 0; o >>= 1) sum += __shfl_xor_sync(0xffffffffu, sum, o);
        float inv = 1.0f / sum;
        float* arow = attn_out + ((size_t)(b * NH + h) * SS + qt * QR + r) * SS;
#pragma unroll
        for (int k = 0; k < 8; k++) {
            float4 p = make_float4(e[k].x * inv, e[k].y * inv, e[k].z * inv, e[k].w * inv);
            *(float4*)&arow[lane * 4 + 128 * k] = p;
            float4 pr = make_float4(rnd_tf32(p.x), rnd_tf32(p.y),
                                    rnd_tf32(p.z), rnd_tf32(p.w));
            *(float4*)&row[lane * 4 + 128 * k] = pr;
        }
    }
    __syncthreads();

    // ---- PV: context = P @ V (V0 already in flight) ----
    float acc2[4];
#pragma unroll
    for (int i = 0; i < 4; i++) acc2[i] = 0.0f;

    for (int vt = 0; vt < SS / KT; vt++) {
        if (vt == 0) { CP_WAIT0(); __syncthreads(); }
        if (vt < SS / KT - 1) {
            const float* src = &Vb[(vt + 1) * KT * DV];
            uint32_t nb = buf_base[(vt + 1) & 1];
#pragma unroll
            for (int p = 0; p < 4; p++) {
                int row = crow + 32 * p;
                cp16(nb + 4u * (uint32_t)(row * SKS + cc4), &src[row * DV + cc4]);
            }
            CP_COMMIT();
        }

        const float* vb = buf_ptr[vt & 1];
#pragma unroll
        for (int ks = 0; ks < 16; ks++) {
            uint32_t ap[4];
            ldsm_x4(ap, sS_base +
                    4u * (uint32_t)((wmt * 16 + lrow) * SSS + vt * KT + ks * 8 + lkc));
            uint32_t bfr[2];
            int ncol = wns * 8 + (lane >> 2);
            int krow = ks * 8 + (lane & 3);
            bfr[0] = __float_as_uint(vb[krow * SKS + ncol]);
            bfr[1] = __float_as_uint(vb[(krow + 4) * SKS + ncol]);
            mma_tf32(acc2, ap, bfr);
        }

        if (vt < SS / KT - 1) { CP_WAIT0(); __syncthreads(); }
    }

    // Write context in [b, s, h*64 + d]
    {
        int r = qt * QR + wmt * 16 + (lane >> 2);
        int col = h * DV + wns * 8 + 2 * (lane & 3);
        *(float2*)&ctx_out[((size_t)b * SS + r) * (NH * DV) + col] =
            make_float2(acc2[0], acc2[1]);
        *(float2*)&ctx_out[((size_t)b * SS + r + 8) * (NH * DV) + col] =
            make_float2(acc2[2], acc2[3]);
    }
}

// ---------------------------------------------------------------------------
// Launch
// ---------------------------------------------------------------------------
extern "C" void kernel_launch(void* const* d_in, const int* in_sizes, int n_in,
                              void* d_out, int out_size)
{
    const float* q  = (const float*)d_in[0];
    const float* k  = (const float*)d_in[1];
    const float* v  = (const float*)d_in[2];
    const float* wq = (const float*)d_in[3];
    const float* wk = (const float*)d_in[4];
    const float* wv = (const float*)d_in[5];
    const float* bq = (const float*)d_in[6];
    const float* bk = (const float*)d_in[7];
    const float* bv = (const float*)d_in[8];
    // d_in[9] = attn_mask (falsy) -> no masking

    float* ctx  = (float*)d_out;
    float* attn = (float*)d_out + (size_t)BB * SS * NH * DV;

    (void)cudaFuncSetAttribute(attn_kernel,
                               cudaFuncAttributeMaxDynamicSharedMemorySize,
                               ATTN_SMEM_BYTES);

    dim3 pgrid(DM / 128, (BB * SS) / 128, 3);
    proj_mma_kernel<<<pgrid, 256>>>(q, k, v, wq, wk, wv, bq, bk, bv);

    dim3 agrid(SS / QR, NH, BB);
    attn_kernel<<<agrid, 512, ATTN_SMEM_BYTES>>>(ctx, attn);
}

// round 9
// speedup vs baseline: 1.7389x; 1.7389x over previous
#include <cuda_runtime.h>
#include <cuda_bf16.h>
#include <cstdint>
#include <math.h>

// Problem dims
#define BB 4
#define SS 1024
#define DM 1024
#define NH 16
#define DK 64
#define DV 64

// Scratch for projected Q/K/V in [b, h, s, d] layout (stored tf32-rounded)
__device__ float g_Q[BB * NH * SS * DK];
__device__ float g_K[BB * NH * SS * DK];
__device__ float g_V[BB * NH * SS * DV];

// ---------------------------------------------------------------------------
// helpers
// ---------------------------------------------------------------------------
__device__ __forceinline__ uint32_t f2tf32(float x) {
    uint32_t r;
    asm("cvt.rna.tf32.f32 %0, %1;" : "=r"(r) : "f"(x));
    return r;
}
__device__ __forceinline__ float rnd_tf32(float x) {
    return __uint_as_float(f2tf32(x));
}

__device__ __forceinline__ void mma_tf32(float c[4], const uint32_t a[4], const uint32_t b[2]) {
    asm volatile(
        "mma.sync.aligned.m16n8k8.row.col.f32.tf32.tf32.f32 "
        "{%0,%1,%2,%3}, {%4,%5,%6,%7}, {%8,%9}, {%0,%1,%2,%3};"
        : "+f"(c[0]), "+f"(c[1]), "+f"(c[2]), "+f"(c[3])
        : "r"(a[0]), "r"(a[1]), "r"(a[2]), "r"(a[3]), "r"(b[0]), "r"(b[1]));
}

__device__ __forceinline__ void ldsm_x4(uint32_t r[4], uint32_t addr) {
    asm volatile("ldmatrix.sync.aligned.m8n8.x4.shared.b16 {%0,%1,%2,%3}, [%4];"
                 : "=r"(r[0]), "=r"(r[1]), "=r"(r[2]), "=r"(r[3]) : "r"(addr));
}

__device__ __forceinline__ void cp16(uint32_t smem, const void* g) {
    asm volatile("cp.async.cg.shared.global [%0], [%1], 16;" :: "r"(smem), "l"(g));
}
#define CP_COMMIT() asm volatile("cp.async.commit_group;")
#define CP_WAIT0()  asm volatile("cp.async.wait_group 0;")
#define CP_WAIT1()  asm volatile("cp.async.wait_group 1;")
#define CP_WAIT2()  asm volatile("cp.async.wait_group 2;")

// ---------------------------------------------------------------------------
// Projection GEMM, tf32 mma.sync (unchanged; measured ~193us).
// ---------------------------------------------------------------------------
#define ASTR 36
#define WSTR 136

__global__ __launch_bounds__(256, 2) void proj_mma_kernel(
    const float* __restrict__ xq, const float* __restrict__ xk, const float* __restrict__ xv,
    const float* __restrict__ wq, const float* __restrict__ wk, const float* __restrict__ wv,
    const float* __restrict__ bq, const float* __restrict__ bk, const float* __restrict__ bv)
{
    __shared__ float As[128 * ASTR];
    __shared__ float Ws[32 * WSTR];

    const float* X; const float* W; const float* bias; float* out;
    int which = blockIdx.z;
    if (which == 0)      { X = xq; W = wq; bias = bq; out = g_Q; }
    else if (which == 1) { X = xk; W = wk; bias = bk; out = g_K; }
    else                 { X = xv; W = wv; bias = bv; out = g_V; }

    const int tid  = threadIdx.x;
    const int warp = tid >> 5;
    const int lane = tid & 31;
    const int wm   = warp >> 2;
    const int wn   = warp & 3;
    const int tileM = blockIdx.y * 128;
    const int tileN = blockIdx.x * 128;

    const int lrow = (lane & 7) + ((lane >> 3) & 1) * 8;
    const int lkc  = (lane >> 4) * 4;
    const int a_lane_off = lrow * ASTR + lkc;

    const uint32_t As_base = (uint32_t)__cvta_generic_to_shared(As);

    float acc[4][4][4];
#pragma unroll
    for (int mt = 0; mt < 4; mt++)
#pragma unroll
        for (int nt = 0; nt < 4; nt++)
#pragma unroll
            for (int i = 0; i < 4; i++) acc[mt][nt][i] = 0.0f;

    float4 xr[4], wr[4];
#pragma unroll
    for (int p = 0; p < 4; p++) {
        int id = tid + 256 * p;
        xr[p] = *(const float4*)&X[(size_t)(tileM + (id >> 3)) * DM + (id & 7) * 4];
        wr[p] = *(const float4*)&W[(size_t)(id >> 5) * DM + tileN + (id & 31) * 4];
    }

    for (int k0 = 0; k0 < DM; k0 += 32) {
        __syncthreads();
#pragma unroll
        for (int p = 0; p < 4; p++) {
            int id = tid + 256 * p;
            float4 xv4 = make_float4(rnd_tf32(xr[p].x), rnd_tf32(xr[p].y),
                                     rnd_tf32(xr[p].z), rnd_tf32(xr[p].w));
            float4 wv4 = make_float4(rnd_tf32(wr[p].x), rnd_tf32(wr[p].y),
                                     rnd_tf32(wr[p].z), rnd_tf32(wr[p].w));
            *(float4*)&As[(id >> 3) * ASTR + (id & 7) * 4] = xv4;
            *(float4*)&Ws[(id >> 5) * WSTR + (id & 31) * 4] = wv4;
        }
        __syncthreads();

        if (k0 + 32 < DM) {
#pragma unroll
            for (int p = 0; p < 4; p++) {
                int id = tid + 256 * p;
                xr[p] = *(const float4*)&X[(size_t)(tileM + (id >> 3)) * DM + k0 + 32 + (id & 7) * 4];
                wr[p] = *(const float4*)&W[(size_t)(k0 + 32 + (id >> 5)) * DM + tileN + (id & 31) * 4];
            }
        }

#pragma unroll
        for (int ks = 0; ks < 4; ks++) {
            uint32_t a[4][4];
#pragma unroll
            for (int mt = 0; mt < 4; mt++) {
                uint32_t addr = As_base +
                    4u * (uint32_t)((wm * 64 + mt * 16) * ASTR + ks * 8 + a_lane_off);
                ldsm_x4(a[mt], addr);
            }
            uint32_t bfr[4][2];
#pragma unroll
            for (int nt = 0; nt < 4; nt++) {
                int col = wn * 32 + nt * 8 + (lane >> 2);
                int krow = ks * 8 + (lane & 3);
                bfr[nt][0] = __float_as_uint(Ws[krow * WSTR + col]);
                bfr[nt][1] = __float_as_uint(Ws[(krow + 4) * WSTR + col]);
            }
#pragma unroll
            for (int mt = 0; mt < 4; mt++)
#pragma unroll
                for (int nt = 0; nt < 4; nt++)
                    mma_tf32(acc[mt][nt], a[mt], bfr[nt]);
        }
    }

#pragma unroll
    for (int mt = 0; mt < 4; mt++) {
        int r0 = tileM + wm * 64 + mt * 16 + (lane >> 2);
#pragma unroll
        for (int nt = 0; nt < 4; nt++) {
            int c0 = tileN + wn * 32 + nt * 8 + (lane & 3) * 2;
            int h = c0 >> 6, d = c0 & 63;
            float bv0 = bias[c0], bv1 = bias[c0 + 1];
#pragma unroll
            for (int half = 0; half < 2; half++) {
                int r = r0 + half * 8;
                int bb = r >> 10, s = r & (SS - 1);
                float2 o = make_float2(rnd_tf32(acc[mt][nt][half * 2 + 0] + bv0),
                                       rnd_tf32(acc[mt][nt][half * 2 + 1] + bv1));
                *(float2*)&out[(((size_t)(bb * NH + h) * SS + s) << 6) + d] = o;
            }
        }
    }
}

// ---------------------------------------------------------------------------
// Fused attention: R5 economics (32 q-rows, 8 warps, full score row in smem)
// with a 4-buffer 64-row-tile cp.async pipeline at prefetch distance 2.
// Global tile index g: 0..15 = K tiles, 16..31 = V tiles. buf = g & 3.
// ---------------------------------------------------------------------------
#define QR 32
#define KTL 64          // K/V tile rows
#define NTK 16          // number of K tiles (= number of V tiles)
#define SQS 68
#define SKS 68
#define SSS 1028
#define BUF_FLOATS (KTL * SKS)
#define ATTN_SMEM_FLOATS (QR * SQS + 4 * BUF_FLOATS + QR * SSS)
#define ATTN_SMEM_BYTES (ATTN_SMEM_FLOATS * 4)

__global__ __launch_bounds__(256, 1) void attn_kernel(
    float* __restrict__ ctx_out, float* __restrict__ attn_out)
{
    extern __shared__ float sm[];
    float* sQ = sm;                       // 32 x 68
    float* sB = sQ + QR * SQS;            // 4 bufs of 64 x 68
    float* sS = sB + 4 * BUF_FLOATS;      // 32 x 1028

    const int tid  = threadIdx.x;
    const int warp = tid >> 5;      // 0..7
    const int lane = tid & 31;
    const int wmt  = warp >> 2;     // 0..1 : m16 tile
    const int wns  = warp & 3;      // 0..3 : 16-col n-slice
    const int qt = blockIdx.x;
    const int h  = blockIdx.y;
    const int b  = blockIdx.z;

    const float* Qb = g_Q + ((size_t)(b * NH + h) * SS + qt * QR) * DK;
    const float* Kb = g_K + (size_t)(b * NH + h) * SS * DK;
    const float* Vb = g_V + (size_t)(b * NH + h) * SS * DV;

    const int lrow = (lane & 7) + ((lane >> 3) & 1) * 8;
    const int lkc  = (lane >> 4) * 4;
    const uint32_t sQ_base = (uint32_t)__cvta_generic_to_shared(sQ);
    const uint32_t sB_base = (uint32_t)__cvta_generic_to_shared(sB);
    const uint32_t sS_base = (uint32_t)__cvta_generic_to_shared(sS);

    // tile-copy coords: 64x64 tile = 1024 float4, 256 threads -> 4 each
    const int crow = tid >> 4;          // 0..15 (+16 per p)
    const int cc4  = (tid & 15) * 4;

    // ---- prologue: Q + K0 (group 0), K1 (group 1) ----
#pragma unroll
    for (int p = 0; p < 2; p++) {
        int row = (tid + 256 * p) >> 4;
        cp16(sQ_base + 4u * (uint32_t)(row * SQS + cc4), &Qb[row * DK + cc4]);
    }
#pragma unroll
    for (int p = 0; p < 4; p++) {
        int row = crow + 16 * p;
        cp16(sB_base + 4u * (uint32_t)(row * SKS + cc4), &Kb[row * DK + cc4]);
    }
    CP_COMMIT();
#pragma unroll
    for (int p = 0; p < 4; p++) {
        int row = crow + 16 * p;
        cp16(sB_base + 4u * (uint32_t)(BUF_FLOATS + row * SKS + cc4),
             &Kb[(KTL + row) * DK + cc4]);
    }
    CP_COMMIT();
    CP_WAIT1();           // group 0 (Q + K0) done
    __syncthreads();

    // Preload Q fragments for this warp's m16 tile (raw bits, pre-rounded)
    uint32_t aq[8][4];
#pragma unroll
    for (int ks = 0; ks < 8; ks++)
        ldsm_x4(aq[ks], sQ_base + 4u * (uint32_t)((wmt * 16 + lrow) * SQS + ks * 8 + lkc));

    // ---- Scores: S = (Q K^T)/8, 16 tiles, prefetch distance 2 ----
    for (int kt = 0; kt < NTK; kt++) {
        {   // issue tile g = kt+2 (K tile, or V tile for g >= 16)
            int g = kt + 2;
            const float* src = (g < NTK) ? &Kb[g * KTL * DK] : &Vb[(g - NTK) * KTL * DV];
            uint32_t nb = sB_base + 4u * (uint32_t)((g & 3) * BUF_FLOATS);
#pragma unroll
            for (int p = 0; p < 4; p++) {
                int row = crow + 16 * p;
                cp16(nb + 4u * (uint32_t)(row * SKS + cc4), &src[row * DK + cc4]);
            }
            CP_COMMIT();
        }
        CP_WAIT2();        // tile kt complete (two younger groups pending)
        __syncthreads();

        const float* kb = sB + (kt & 3) * BUF_FLOATS;
        float c[2][4];
#pragma unroll
        for (int nt = 0; nt < 2; nt++)
#pragma unroll
            for (int i = 0; i < 4; i++) c[nt][i] = 0.0f;

#pragma unroll
        for (int ks = 0; ks < 8; ks++) {
            uint32_t bfr[2][2];
#pragma unroll
            for (int nt = 0; nt < 2; nt++) {
                int ncol = wns * 16 + nt * 8 + (lane >> 2);
                int krow = ks * 8 + (lane & 3);
                bfr[nt][0] = __float_as_uint(kb[ncol * SKS + krow]);
                bfr[nt][1] = __float_as_uint(kb[ncol * SKS + krow + 4]);
            }
            mma_tf32(c[0], aq[ks], bfr[0]);
            mma_tf32(c[1], aq[ks], bfr[1]);
        }
#pragma unroll
        for (int nt = 0; nt < 2; nt++) {
            int r = wmt * 16 + (lane >> 2);
            int col = kt * KTL + wns * 16 + nt * 8 + 2 * (lane & 3);
            *(float2*)&sS[r * SSS + col] = make_float2(c[nt][0] * 0.125f, c[nt][1] * 0.125f);
            *(float2*)&sS[(r + 8) * SSS + col] = make_float2(c[nt][2] * 0.125f, c[nt][3] * 0.125f);
        }
    }
    __syncthreads();    // all S visible (V0/V1 loads still in flight)

    // ---- Softmax (4 rows/warp); raw P -> gmem, tf32 P -> smem ----
#pragma unroll
    for (int rr = 0; rr < 4; rr++) {
        int r = warp * 4 + rr;
        float* row = sS + r * SSS;
        float mx = -3.0e38f;
#pragma unroll
        for (int k = 0; k < 8; k++) {
            float4 v = *(const float4*)&row[lane * 4 + 128 * k];
            mx = fmaxf(mx, fmaxf(fmaxf(v.x, v.y), fmaxf(v.z, v.w)));
        }
#pragma unroll
        for (int o = 16; o > 0; o >>= 1) mx = fmaxf(mx, __shfl_xor_sync(0xffffffffu, mx, o));
        float sum = 0.0f;
        float4 e[8];
#pragma unroll
        for (int k = 0; k < 8; k++) {
            float4 v = *(const float4*)&row[lane * 4 + 128 * k];
            e[k].x = __expf(v.x - mx); e[k].y = __expf(v.y - mx);
            e[k].z = __expf(v.z - mx); e[k].w = __expf(v.w - mx);
            sum += e[k].x + e[k].y + e[k].z + e[k].w;
        }
#pragma unroll
        for (int o = 16; o > 0; o >>= 1) sum += __shfl_xor_sync(0xffffffffu, sum, o);
        float inv = 1.0f / sum;
        float* arow = attn_out + ((size_t)(b * NH + h) * SS + qt * QR + r) * SS;
#pragma unroll
        for (int k = 0; k < 8; k++) {
            float4 p = make_float4(e[k].x * inv, e[k].y * inv, e[k].z * inv, e[k].w * inv);
            *(float4*)&arow[lane * 4 + 128 * k] = p;
            float4 pr = make_float4(rnd_tf32(p.x), rnd_tf32(p.y),
                                    rnd_tf32(p.z), rnd_tf32(p.w));
            *(float4*)&row[lane * 4 + 128 * k] = pr;
        }
    }

    // ---- PV: context = P @ V, 16 V tiles, prefetch distance 2 ----
    float acc2[2][4];
#pragma unroll
    for (int nt = 0; nt < 2; nt++)
#pragma unroll
        for (int i = 0; i < 4; i++) acc2[nt][i] = 0.0f;

    for (int vt = 0; vt < NTK; vt++) {
        if (vt + 2 < NTK) {    // issue V tile vt+2 (g = 18+vt)
            const float* src = &Vb[(vt + 2) * KTL * DV];
            uint32_t nb = sB_base + 4u * (uint32_t)(((vt + 2) & 3) * BUF_FLOATS);
#pragma unroll
            for (int p = 0; p < 4; p++) {
                int row = crow + 16 * p;
                cp16(nb + 4u * (uint32_t)(row * SKS + cc4), &src[row * DV + cc4]);
            }
            CP_COMMIT();
        }
        if (vt < NTK - 2)      CP_WAIT2();
        else if (vt == NTK - 2) CP_WAIT1();
        else                   CP_WAIT0();
        __syncthreads();

        const float* vb = sB + (vt & 3) * BUF_FLOATS;
#pragma unroll
        for (int ks = 0; ks < 8; ks++) {
            uint32_t ap[4];
            ldsm_x4(ap, sS_base +
                    4u * (uint32_t)((wmt * 16 + lrow) * SSS + vt * KTL + ks * 8 + lkc));
            uint32_t bfr[2][2];
#pragma unroll
            for (int nt = 0; nt < 2; nt++) {
                int ncol = wns * 16 + nt * 8 + (lane >> 2);
                int krow = ks * 8 + (lane & 3);
                bfr[nt][0] = __float_as_uint(vb[krow * SKS + ncol]);
                bfr[nt][1] = __float_as_uint(vb[(krow + 4) * SKS + ncol]);
            }
            mma_tf32(acc2[0], ap, bfr[0]);
            mma_tf32(acc2[1], ap, bfr[1]);
        }
    }

    // Write context in [b, s, h*64 + d]
#pragma unroll
    for (int nt = 0; nt < 2; nt++) {
        int r = qt * QR + wmt * 16 + (lane >> 2);
        int col = h * DV + wns * 16 + nt * 8 + 2 * (lane & 3);
        *(float2*)&ctx_out[((size_t)b * SS + r) * (NH * DV) + col] =
            make_float2(acc2[nt][0], acc2[nt][1]);
        *(float2*)&ctx_out[((size_t)b * SS + r + 8) * (NH * DV) + col] =
            make_float2(acc2[nt][2], acc2[nt][3]);
    }
}

// ---------------------------------------------------------------------------
// Launch
// ---------------------------------------------------------------------------
extern "C" void kernel_launch(void* const* d_in, const int* in_sizes, int n_in,
                              void* d_out, int out_size)
{
    const float* q  = (const float*)d_in[0];
    const float* k  = (const float*)d_in[1];
    const float* v  = (const float*)d_in[2];
    const float* wq = (const float*)d_in[3];
    const float* wk = (const float*)d_in[4];
    const float* wv = (const float*)d_in[5];
    const float* bq = (const float*)d_in[6];
    const float* bk = (const float*)d_in[7];
    const float* bv = (const float*)d_in[8];
    // d_in[9] = attn_mask (falsy) -> no masking

    float* ctx  = (float*)d_out;
    float* attn = (float*)d_out + (size_t)BB * SS * NH * DV;

    (void)cudaFuncSetAttribute(attn_kernel,
                               cudaFuncAttributeMaxDynamicSharedMemorySize,
                               ATTN_SMEM_BYTES);

    dim3 pgrid(DM / 128, (BB * SS) / 128, 3);
    proj_mma_kernel<<<pgrid, 256>>>(q, k, v, wq, wk, wv, bq, bk, bv);

    dim3 agrid(SS / QR, NH, BB);
    attn_kernel<<<agrid, 256, ATTN_SMEM_BYTES>>>(ctx, attn);
}

// round 11
// speedup vs baseline: 1.7459x; 1.0040x over previous
#include <cuda_runtime.h>
#include <cuda_bf16.h>
#include <cstdint>
#include <math.h>

// Problem dims
#define BB 4
#define SS 1024
#define DM 1024
#define NH 16
#define DK 64
#define DV 64

// Scratch for projected Q/K/V in [b, h, s, d] layout (stored tf32-rounded)
__device__ float g_Q[BB * NH * SS * DK];
__device__ float g_K[BB * NH * SS * DK];
__device__ float g_V[BB * NH * SS * DV];

// ---------------------------------------------------------------------------
// helpers
// ---------------------------------------------------------------------------
__device__ __forceinline__ uint32_t f2tf32(float x) {
    uint32_t r;
    asm("cvt.rna.tf32.f32 %0, %1;" : "=r"(r) : "f"(x));
    return r;
}
__device__ __forceinline__ float rnd_tf32(float x) {
    return __uint_as_float(f2tf32(x));
}

__device__ __forceinline__ void mma_tf32(float c[4], const uint32_t a[4], const uint32_t b[2]) {
    asm volatile(
        "mma.sync.aligned.m16n8k8.row.col.f32.tf32.tf32.f32 "
        "{%0,%1,%2,%3}, {%4,%5,%6,%7}, {%8,%9}, {%0,%1,%2,%3};"
        : "+f"(c[0]), "+f"(c[1]), "+f"(c[2]), "+f"(c[3])
        : "r"(a[0]), "r"(a[1]), "r"(a[2]), "r"(a[3]), "r"(b[0]), "r"(b[1]));
}

__device__ __forceinline__ void ldsm_x4(uint32_t r[4], uint32_t addr) {
    asm volatile("ldmatrix.sync.aligned.m8n8.x4.shared.b16 {%0,%1,%2,%3}, [%4];"
                 : "=r"(r[0]), "=r"(r[1]), "=r"(r[2]), "=r"(r[3]) : "r"(addr));
}

__device__ __forceinline__ void cp16(uint32_t smem, const void* g) {
    asm volatile("cp.async.cg.shared.global [%0], [%1], 16;" :: "r"(smem), "l"(g));
}
#define CP_COMMIT() asm volatile("cp.async.commit_group;")
#define CP_WAIT0()  asm volatile("cp.async.wait_group 0;")
#define CP_WAIT1()  asm volatile("cp.async.wait_group 1;")
#define CP_WAIT2()  asm volatile("cp.async.wait_group 2;")

// ---------------------------------------------------------------------------
// Projection GEMM, tf32 mma.sync (unchanged; measured ~195us).
// ---------------------------------------------------------------------------
#define ASTR 36
#define WSTR 136

__global__ __launch_bounds__(256, 2) void proj_mma_kernel(
    const float* __restrict__ xq, const float* __restrict__ xk, const float* __restrict__ xv,
    const float* __restrict__ wq, const float* __restrict__ wk, const float* __restrict__ wv,
    const float* __restrict__ bq, const float* __restrict__ bk, const float* __restrict__ bv)
{
    __shared__ float As[128 * ASTR];
    __shared__ float Ws[32 * WSTR];

    const float* X; const float* W; const float* bias; float* out;
    int which = blockIdx.z;
    if (which == 0)      { X = xq; W = wq; bias = bq; out = g_Q; }
    else if (which == 1) { X = xk; W = wk; bias = bk; out = g_K; }
    else                 { X = xv; W = wv; bias = bv; out = g_V; }

    const int tid  = threadIdx.x;
    const int warp = tid >> 5;
    const int lane = tid & 31;
    const int wm   = warp >> 2;
    const int wn   = warp & 3;
    const int tileM = blockIdx.y * 128;
    const int tileN = blockIdx.x * 128;

    const int lrow = (lane & 7) + ((lane >> 3) & 1) * 8;
    const int lkc  = (lane >> 4) * 4;
    const int a_lane_off = lrow * ASTR + lkc;

    const uint32_t As_base = (uint32_t)__cvta_generic_to_shared(As);

    float acc[4][4][4];
#pragma unroll
    for (int mt = 0; mt < 4; mt++)
#pragma unroll
        for (int nt = 0; nt < 4; nt++)
#pragma unroll
            for (int i = 0; i < 4; i++) acc[mt][nt][i] = 0.0f;

    float4 xr[4], wr[4];
#pragma unroll
    for (int p = 0; p < 4; p++) {
        int id = tid + 256 * p;
        xr[p] = *(const float4*)&X[(size_t)(tileM + (id >> 3)) * DM + (id & 7) * 4];
        wr[p] = *(const float4*)&W[(size_t)(id >> 5) * DM + tileN + (id & 31) * 4];
    }

    for (int k0 = 0; k0 < DM; k0 += 32) {
        __syncthreads();
#pragma unroll
        for (int p = 0; p < 4; p++) {
            int id = tid + 256 * p;
            float4 xv4 = make_float4(rnd_tf32(xr[p].x), rnd_tf32(xr[p].y),
                                     rnd_tf32(xr[p].z), rnd_tf32(xr[p].w));
            float4 wv4 = make_float4(rnd_tf32(wr[p].x), rnd_tf32(wr[p].y),
                                     rnd_tf32(wr[p].z), rnd_tf32(wr[p].w));
            *(float4*)&As[(id >> 3) * ASTR + (id & 7) * 4] = xv4;
            *(float4*)&Ws[(id >> 5) * WSTR + (id & 31) * 4] = wv4;
        }
        __syncthreads();

        if (k0 + 32 < DM) {
#pragma unroll
            for (int p = 0; p < 4; p++) {
                int id = tid + 256 * p;
                xr[p] = *(const float4*)&X[(size_t)(tileM + (id >> 3)) * DM + k0 + 32 + (id & 7) * 4];
                wr[p] = *(const float4*)&W[(size_t)(k0 + 32 + (id >> 5)) * DM + tileN + (id & 31) * 4];
            }
        }

#pragma unroll
        for (int ks = 0; ks < 4; ks++) {
            uint32_t a[4][4];
#pragma unroll
            for (int mt = 0; mt < 4; mt++) {
                uint32_t addr = As_base +
                    4u * (uint32_t)((wm * 64 + mt * 16) * ASTR + ks * 8 + a_lane_off);
                ldsm_x4(a[mt], addr);
            }
            uint32_t bfr[4][2];
#pragma unroll
            for (int nt = 0; nt < 4; nt++) {
                int col = wn * 32 + nt * 8 + (lane >> 2);
                int krow = ks * 8 + (lane & 3);
                bfr[nt][0] = __float_as_uint(Ws[krow * WSTR + col]);
                bfr[nt][1] = __float_as_uint(Ws[(krow + 4) * WSTR + col]);
            }
#pragma unroll
            for (int mt = 0; mt < 4; mt++)
#pragma unroll
                for (int nt = 0; nt < 4; nt++)
                    mma_tf32(acc[mt][nt], a[mt], bfr[nt]);
        }
    }

#pragma unroll
    for (int mt = 0; mt < 4; mt++) {
        int r0 = tileM + wm * 64 + mt * 16 + (lane >> 2);
#pragma unroll
        for (int nt = 0; nt < 4; nt++) {
            int c0 = tileN + wn * 32 + nt * 8 + (lane & 3) * 2;
            int h = c0 >> 6, d = c0 & 63;
            float bv0 = bias[c0], bv1 = bias[c0 + 1];
#pragma unroll
            for (int half = 0; half < 2; half++) {
                int r = r0 + half * 8;
                int bb = r >> 10, s = r & (SS - 1);
                float2 o = make_float2(rnd_tf32(acc[mt][nt][half * 2 + 0] + bv0),
                                       rnd_tf32(acc[mt][nt][half * 2 + 1] + bv1));
                *(float2*)&out[(((size_t)(bb * NH + h) * SS + s) << 6) + d] = o;
            }
        }
    }
}

// ---------------------------------------------------------------------------
// Fused attention: 32 q-rows, 8 warps, full score row in smem,
// 4-buffer 64-row-tile cp.async pipeline (prefetch distance 2).
// Scores: B-fragments via ldmatrix.x4 (conflict-free, 1 instr / ks).
// PV: even/odd-ks split accumulators to halve the mma dependency chain.
// ---------------------------------------------------------------------------
#define QR 32
#define KTL 64          // K/V tile rows
#define NTK 16          // number of K tiles (= number of V tiles)
#define SQS 68
#define SKS 68
#define SSS 1028
#define BUF_FLOATS (KTL * SKS)
#define ATTN_SMEM_FLOATS (QR * SQS + 4 * BUF_FLOATS + QR * SSS)
#define ATTN_SMEM_BYTES (ATTN_SMEM_FLOATS * 4)

__global__ __launch_bounds__(256, 1) void attn_kernel(
    float* __restrict__ ctx_out, float* __restrict__ attn_out)
{
    extern __shared__ float sm[];
    float* sQ = sm;                       // 32 x 68
    float* sB = sQ + QR * SQS;            // 4 bufs of 64 x 68
    float* sS = sB + 4 * BUF_FLOATS;      // 32 x 1028

    const int tid  = threadIdx.x;
    const int warp = tid >> 5;      // 0..7
    const int lane = tid & 31;
    const int wmt  = warp >> 2;     // 0..1 : m16 tile
    const int wns  = warp & 3;      // 0..3 : 16-col n-slice
    const int qt = blockIdx.x;
    const int h  = blockIdx.y;
    const int b  = blockIdx.z;

    const float* Qb = g_Q + ((size_t)(b * NH + h) * SS + qt * QR) * DK;
    const float* Kb = g_K + (size_t)(b * NH + h) * SS * DK;
    const float* Vb = g_V + (size_t)(b * NH + h) * SS * DV;

    const int lrow = (lane & 7) + ((lane >> 3) & 1) * 8;
    const int lkc  = (lane >> 4) * 4;
    const uint32_t sQ_base = (uint32_t)__cvta_generic_to_shared(sQ);
    const uint32_t sB_base = (uint32_t)__cvta_generic_to_shared(sB);
    const uint32_t sS_base = (uint32_t)__cvta_generic_to_shared(sS);

    // ldmatrix.x4 B-fragment lane address within a K tile buffer:
    // block j = lane>>3 : (nt = j>>1, khalf = j&1), row-in-block = lane&7.
    // r0,r1 = nt0 {k0-3,k4-7}; r2,r3 = nt1.
    const int bj = lane >> 3;
    const int b_lane_off = (wns * 16 + (bj >> 1) * 8 + (lane & 7)) * SKS + (bj & 1) * 4;

    // tile-copy coords: 64x64 tile = 1024 float4, 256 threads -> 4 each
    const int crow = tid >> 4;          // 0..15 (+16 per p)
    const int cc4  = (tid & 15) * 4;

    // ---- prologue: Q + K0 (group 0), K1 (group 1) ----
#pragma unroll
    for (int p = 0; p < 2; p++) {
        int row = (tid + 256 * p) >> 4;
        cp16(sQ_base + 4u * (uint32_t)(row * SQS + cc4), &Qb[row * DK + cc4]);
    }
#pragma unroll
    for (int p = 0; p < 4; p++) {
        int row = crow + 16 * p;
        cp16(sB_base + 4u * (uint32_t)(row * SKS + cc4), &Kb[row * DK + cc4]);
    }
    CP_COMMIT();
#pragma unroll
    for (int p = 0; p < 4; p++) {
        int row = crow + 16 * p;
        cp16(sB_base + 4u * (uint32_t)(BUF_FLOATS + row * SKS + cc4),
             &Kb[(KTL + row) * DK + cc4]);
    }
    CP_COMMIT();
    CP_WAIT1();           // group 0 (Q + K0) done
    __syncthreads();

    // Preload Q fragments for this warp's m16 tile (raw bits, pre-rounded)
    uint32_t aq[8][4];
#pragma unroll
    for (int ks = 0; ks < 8; ks++)
        ldsm_x4(aq[ks], sQ_base + 4u * (uint32_t)((wmt * 16 + lrow) * SQS + ks * 8 + lkc));

    // ---- Scores: S = (Q K^T)/8, 16 tiles, prefetch distance 2 ----
    for (int kt = 0; kt < NTK; kt++) {
        {   // issue tile g = kt+2 (K tile, or V tile for g >= 16)
            int g = kt + 2;
            const float* src = (g < NTK) ? &Kb[g * KTL * DK] : &Vb[(g - NTK) * KTL * DV];
            uint32_t nb = sB_base + 4u * (uint32_t)((g & 3) * BUF_FLOATS);
#pragma unroll
            for (int p = 0; p < 4; p++) {
                int row = crow + 16 * p;
                cp16(nb + 4u * (uint32_t)(row * SKS + cc4), &src[row * DK + cc4]);
            }
            CP_COMMIT();
        }
        CP_WAIT2();        // tile kt complete (two younger groups pending)
        __syncthreads();

        const uint32_t kb_base = sB_base + 4u * (uint32_t)((kt & 3) * BUF_FLOATS + b_lane_off);
        float c[2][4];
#pragma unroll
        for (int nt = 0; nt < 2; nt++)
#pragma unroll
            for (int i = 0; i < 4; i++) c[nt][i] = 0.0f;

#pragma unroll
        for (int ks = 0; ks < 8; ks++) {
            uint32_t bfr[4];
            ldsm_x4(bfr, kb_base + 4u * (uint32_t)(ks * 8));
            mma_tf32(c[0], aq[ks], &bfr[0]);
            mma_tf32(c[1], aq[ks], &bfr[2]);
        }
#pragma unroll
        for (int nt = 0; nt < 2; nt++) {
            int r = wmt * 16 + (lane >> 2);
            int col = kt * KTL + wns * 16 + nt * 8 + 2 * (lane & 3);
            *(float2*)&sS[r * SSS + col] = make_float2(c[nt][0] * 0.125f, c[nt][1] * 0.125f);
            *(float2*)&sS[(r + 8) * SSS + col] = make_float2(c[nt][2] * 0.125f, c[nt][3] * 0.125f);
        }
    }
    __syncthreads();    // all S visible (V0/V1 loads still in flight)

    // ---- Softmax (4 rows/warp); raw P -> gmem, tf32 P -> smem ----
#pragma unroll
    for (int rr = 0; rr < 4; rr++) {
        int r = warp * 4 + rr;
        float* row = sS + r * SSS;
        float mx = -3.0e38f;
#pragma unroll
        for (int k = 0; k < 8; k++) {
            float4 v = *(const float4*)&row[lane * 4 + 128 * k];
            mx = fmaxf(mx, fmaxf(fmaxf(v.x, v.y), fmaxf(v.z, v.w)));
        }
#pragma unroll
        for (int o = 16; o > 0; o >>= 1) mx = fmaxf(mx, __shfl_xor_sync(0xffffffffu, mx, o));
        float sum = 0.0f;
        float4 e[8];
#pragma unroll
        for (int k = 0; k < 8; k++) {
            float4 v = *(const float4*)&row[lane * 4 + 128 * k];
            e[k].x = __expf(v.x - mx); e[k].y = __expf(v.y - mx);
            e[k].z = __expf(v.z - mx); e[k].w = __expf(v.w - mx);
            sum += e[k].x + e[k].y + e[k].z + e[k].w;
        }
#pragma unroll
        for (int o = 16; o > 0; o >>= 1) sum += __shfl_xor_sync(0xffffffffu, sum, o);
        float inv = 1.0f / sum;
        float* arow = attn_out + ((size_t)(b * NH + h) * SS + qt * QR + r) * SS;
#pragma unroll
        for (int k = 0; k < 8; k++) {
            float4 p = make_float4(e[k].x * inv, e[k].y * inv, e[k].z * inv, e[k].w * inv);
            *(float4*)&arow[lane * 4 + 128 * k] = p;
            float4 pr = make_float4(rnd_tf32(p.x), rnd_tf32(p.y),
                                    rnd_tf32(p.z), rnd_tf32(p.w));
            *(float4*)&row[lane * 4 + 128 * k] = pr;
        }
    }

    // ---- PV: context = P @ V, 16 V tiles, prefetch distance 2 ----
    // Even/odd-ks accumulator split halves the RAW mma chain.
    float acc2[2][2][4];   // [nt][parity][4]
#pragma unroll
    for (int nt = 0; nt < 2; nt++)
#pragma unroll
        for (int par = 0; par < 2; par++)
#pragma unroll
            for (int i = 0; i < 4; i++) acc2[nt][par][i] = 0.0f;

    for (int vt = 0; vt < NTK; vt++) {
        if (vt + 2 < NTK) {    // issue V tile vt+2
            const float* src = &Vb[(vt + 2) * KTL * DV];
            uint32_t nb = sB_base + 4u * (uint32_t)(((vt + 2) & 3) * BUF_FLOATS);
#pragma unroll
            for (int p = 0; p < 4; p++) {
                int row = crow + 16 * p;
                cp16(nb + 4u * (uint32_t)(row * SKS + cc4), &src[row * DV + cc4]);
            }
            CP_COMMIT();
        }
        if (vt < NTK - 2)      CP_WAIT2();
        else if (vt == NTK - 2) CP_WAIT1();
        else                   CP_WAIT0();
        __syncthreads();

        const float* vb = sB + (vt & 3) * BUF_FLOATS;
#pragma unroll
        for (int ks = 0; ks < 8; ks++) {
            uint32_t ap[4];
            ldsm_x4(ap, sS_base +
                    4u * (uint32_t)((wmt * 16 + lrow) * SSS + vt * KTL + ks * 8 + lkc));
            uint32_t bfr[2][2];
#pragma unroll
            for (int nt = 0; nt < 2; nt++) {
                int ncol = wns * 16 + nt * 8 + (lane >> 2);
                int krow = ks * 8 + (lane & 3);
                bfr[nt][0] = __float_as_uint(vb[krow * SKS + ncol]);
                bfr[nt][1] = __float_as_uint(vb[(krow + 4) * SKS + ncol]);
            }
            mma_tf32(acc2[0][ks & 1], ap, bfr[0]);
            mma_tf32(acc2[1][ks & 1], ap, bfr[1]);
        }
    }

    // Write context in [b, s, h*64 + d] (merge parity accumulators)
#pragma unroll
    for (int nt = 0; nt < 2; nt++) {
        int r = qt * QR + wmt * 16 + (lane >> 2);
        int col = h * DV + wns * 16 + nt * 8 + 2 * (lane & 3);
        *(float2*)&ctx_out[((size_t)b * SS + r) * (NH * DV) + col] =
            make_float2(acc2[nt][0][0] + acc2[nt][1][0],
                        acc2[nt][0][1] + acc2[nt][1][1]);
        *(float2*)&ctx_out[((size_t)b * SS + r + 8) * (NH * DV) + col] =
            make_float2(acc2[nt][0][2] + acc2[nt][1][2],
                        acc2[nt][0][3] + acc2[nt][1][3]);
    }
}

// ---------------------------------------------------------------------------
// Launch
// ---------------------------------------------------------------------------
extern "C" void kernel_launch(void* const* d_in, const int* in_sizes, int n_in,
                              void* d_out, int out_size)
{
    const float* q  = (const float*)d_in[0];
    const float* k  = (const float*)d_in[1];
    const float* v  = (const float*)d_in[2];
    const float* wq = (const float*)d_in[3];
    const float* wk = (const float*)d_in[4];
    const float* wv = (const float*)d_in[5];
    const float* bq = (const float*)d_in[6];
    const float* bk = (const float*)d_in[7];
    const float* bv = (const float*)d_in[8];
    // d_in[9] = attn_mask (falsy) -> no masking

    float* ctx  = (float*)d_out;
    float* attn = (float*)d_out + (size_t)BB * SS * NH * DV;

    (void)cudaFuncSetAttribute(attn_kernel,
                               cudaFuncAttributeMaxDynamicSharedMemorySize,
                               ATTN_SMEM_BYTES);

    dim3 pgrid(DM / 128, (BB * SS) / 128, 3);
    proj_mma_kernel<<<pgrid, 256>>>(q, k, v, wq, wk, wv, bq, bk, bv);

    dim3 agrid(SS / QR, NH, BB);
    attn_kernel<<<agrid, 256, ATTN_SMEM_BYTES>>>(ctx, attn);
}